// round 1
// baseline (speedup 1.0000x reference)
#include <cuda_runtime.h>
#include <mma.h>
#include <math.h>

using namespace nvcuda;

// Problem sizes (hardcoded from reference): B=4, S=2048, D=N=2048
#define BSZ 4
#define SSZ 2048
#define DSZ 2048
#define NSZ 2048
#define MSZ (BSZ * SSZ)   // 8192

#define NCHUNK 16
#define CLEN (SSZ / NCHUNK)  // 128

// Scratch (device globals; no allocation allowed)
__device__ float g_buf0[(size_t)MSZ * NSZ];  // dt_lin -> A_bar (in place)
__device__ float g_buf1[(size_t)MSZ * NSZ];  // Bp     -> inputs (in place)
__device__ float g_h[(size_t)MSZ * NSZ];     // h_all
__device__ float g_prod[BSZ * NCHUNK * NSZ];
__device__ float g_hend[BSZ * NCHUNK * NSZ];
__device__ float g_hin[BSZ * NCHUNK * NSZ];

// ---------------------------------------------------------------------------
// TF32 WMMA GEMM (NT): C[m][n] = sum_k A[m][k] * W[n][k]
// A: [M,K] row-major, W: [N,K] row-major, C: [M,N] row-major
// Block tile 128x128, BK=16, 8 warps, each warp 64x32 (4x2 wmma 16x16 frags)
// ---------------------------------------------------------------------------
#define BM 128
#define BN 128
#define BK 16
#define SPAD 20   // padded row stride for smem tiles (multiple of 4)

__global__ __launch_bounds__(256) void gemm_tf32_nt(
    const float* __restrict__ A, const float* __restrict__ W,
    float* __restrict__ C, int M, int N, int K)
{
    __shared__ float As[BM][SPAD];
    __shared__ float Bs[BN][SPAD];

    const int tid = threadIdx.x;
    const int wid = tid >> 5;
    const int m0 = blockIdx.y * BM;
    const int n0 = blockIdx.x * BN;
    const int wm = (wid >> 2) * 64;  // warp grid 2 (m) x 4 (n)
    const int wn = (wid & 3) * 32;

    wmma::fragment<wmma::accumulator, 16, 16, 8, float> cf[4][2];
    #pragma unroll
    for (int i = 0; i < 4; i++)
        #pragma unroll
        for (int j = 0; j < 2; j++)
            wmma::fill_fragment(cf[i][j], 0.0f);

    for (int k0 = 0; k0 < K; k0 += BK) {
        // Load 128x16 fp32 tiles (512 float4 each), 2 float4 per thread per tile
        #pragma unroll
        for (int s = tid; s < 512; s += 256) {
            int r = s >> 2, cq = (s & 3) * 4;
            float4 v = *(const float4*)(A + (size_t)(m0 + r) * K + k0 + cq);
            *(float4*)&As[r][cq] = v;
        }
        #pragma unroll
        for (int s = tid; s < 512; s += 256) {
            int r = s >> 2, cq = (s & 3) * 4;
            float4 v = *(const float4*)(W + (size_t)(n0 + r) * K + k0 + cq);
            *(float4*)&Bs[r][cq] = v;
        }
        __syncthreads();

        #pragma unroll
        for (int kk = 0; kk < BK; kk += 8) {
            wmma::fragment<wmma::matrix_a, 16, 16, 8, wmma::precision::tf32,
                           wmma::row_major> af[4];
            wmma::fragment<wmma::matrix_b, 16, 16, 8, wmma::precision::tf32,
                           wmma::col_major> bf[2];
            #pragma unroll
            for (int i = 0; i < 4; i++) {
                wmma::load_matrix_sync(af[i], &As[wm + 16 * i][kk], SPAD);
                #pragma unroll
                for (int t = 0; t < af[i].num_elements; t++)
                    af[i].x[t] = wmma::__float_to_tf32(af[i].x[t]);
            }
            #pragma unroll
            for (int j = 0; j < 2; j++) {
                // col_major: element (k, n) at ptr[n*ldm + k]; Bs is [n][k]
                wmma::load_matrix_sync(bf[j], &Bs[wn + 16 * j][kk], SPAD);
                #pragma unroll
                for (int t = 0; t < bf[j].num_elements; t++)
                    bf[j].x[t] = wmma::__float_to_tf32(bf[j].x[t]);
            }
            #pragma unroll
            for (int i = 0; i < 4; i++)
                #pragma unroll
                for (int j = 0; j < 2; j++)
                    wmma::mma_sync(cf[i][j], af[i], bf[j], cf[i][j]);
        }
        __syncthreads();
    }

    #pragma unroll
    for (int i = 0; i < 4; i++)
        #pragma unroll
        for (int j = 0; j < 2; j++)
            wmma::store_matrix_sync(
                C + (size_t)(m0 + wm + 16 * i) * N + n0 + wn + 16 * j,
                cf[i][j], N, wmma::mem_row_major);
}

// ---------------------------------------------------------------------------
// Elementwise: dt = softplus(dt_lin + b_dt); A_bar = exp(dt * -exp(A_log));
//              inputs = dt * Bp * x    (in-place into g_buf0/g_buf1)
// ---------------------------------------------------------------------------
__global__ void elem_kernel(const float* __restrict__ x,
                            const float* __restrict__ b_dt,
                            const float* __restrict__ A_log)
{
    size_t idx = (size_t)blockIdx.x * blockDim.x + threadIdx.x;
    int n = (int)(idx & (NSZ - 1));
    float dtl = g_buf0[idx] + b_dt[n];
    float dt = (dtl > 20.0f) ? dtl : log1pf(expf(dtl));
    float Aa = -expf(A_log[n]);
    float abar = expf(dt * Aa);
    float inp = dt * g_buf1[idx] * x[idx];
    g_buf0[idx] = abar;
    g_buf1[idx] = inp;
}

// ---------------------------------------------------------------------------
// Chunked scan: h_t = A_bar_t * h_{t-1} + inputs_t
// ---------------------------------------------------------------------------
__global__ void scan_pass1()
{
    int gid = blockIdx.x * blockDim.x + threadIdx.x;  // B*NCHUNK*N lanes
    int n = gid & (NSZ - 1);
    int c = (gid >> 11) & (NCHUNK - 1);
    int b = gid >> 15;  // gid / (NSZ*NCHUNK)
    size_t base = ((size_t)(b * SSZ + c * CLEN)) * NSZ + n;
    float h = 0.0f, p = 1.0f;
    #pragma unroll 4
    for (int t = 0; t < CLEN; t++) {
        float ab = g_buf0[base];
        float u  = g_buf1[base];
        h = ab * h + u;
        p *= ab;
        base += NSZ;
    }
    g_prod[gid] = p;
    g_hend[gid] = h;
}

__global__ void scan_pass2()
{
    int gid = blockIdx.x * blockDim.x + threadIdx.x;  // B*N lanes
    int n = gid & (NSZ - 1);
    int b = gid >> 11;
    float hin = 0.0f;
    #pragma unroll
    for (int c = 0; c < NCHUNK; c++) {
        int ci = (b * NCHUNK + c) * NSZ + n;
        g_hin[ci] = hin;
        hin = g_prod[ci] * hin + g_hend[ci];
    }
}

__global__ void scan_pass3()
{
    int gid = blockIdx.x * blockDim.x + threadIdx.x;
    int n = gid & (NSZ - 1);
    int c = (gid >> 11) & (NCHUNK - 1);
    int b = gid >> 15;
    size_t base = ((size_t)(b * SSZ + c * CLEN)) * NSZ + n;
    float h = g_hin[gid];
    #pragma unroll 4
    for (int t = 0; t < CLEN; t++) {
        float ab = g_buf0[base];
        float u  = g_buf1[base];
        h = ab * h + u;
        g_h[base] = h;
        base += NSZ;
    }
}

// ---------------------------------------------------------------------------
// Skip connection: out += D_skip[d] * x
// ---------------------------------------------------------------------------
__global__ void skip_kernel(float* __restrict__ out,
                            const float* __restrict__ x,
                            const float* __restrict__ Dsk)
{
    size_t idx = (size_t)blockIdx.x * blockDim.x + threadIdx.x;
    int d = (int)(idx & (DSZ - 1));
    out[idx] += Dsk[d] * x[idx];
}

// ---------------------------------------------------------------------------
extern "C" void kernel_launch(void* const* d_in, const int* in_sizes, int n_in,
                              void* d_out, int out_size)
{
    const float* x      = (const float*)d_in[0];
    const float* W_dt   = (const float*)d_in[1];
    const float* b_dt   = (const float*)d_in[2];
    const float* W_B    = (const float*)d_in[3];
    const float* W_C    = (const float*)d_in[4];
    const float* A_log  = (const float*)d_in[5];
    const float* D_skip = (const float*)d_in[6];
    float* out = (float*)d_out;

    float *buf0, *buf1, *hbuf;
    cudaGetSymbolAddress((void**)&buf0, g_buf0);
    cudaGetSymbolAddress((void**)&buf1, g_buf1);
    cudaGetSymbolAddress((void**)&hbuf, g_h);

    dim3 grid(NSZ / BN, MSZ / BM);

    // dt_lin = x @ W_dt^T ; Bp = x @ W_B^T
    gemm_tf32_nt<<<grid, 256>>>(x, W_dt, buf0, MSZ, NSZ, DSZ);
    gemm_tf32_nt<<<grid, 256>>>(x, W_B,  buf1, MSZ, NSZ, DSZ);

    // elementwise: A_bar, inputs
    elem_kernel<<<(MSZ * NSZ) / 256, 256>>>(x, b_dt, A_log);

    // chunked selective scan
    scan_pass1<<<(BSZ * NCHUNK * NSZ) / 256, 256>>>();
    scan_pass2<<<(BSZ * NSZ) / 256, 256>>>();
    scan_pass3<<<(BSZ * NCHUNK * NSZ) / 256, 256>>>();

    // out = h @ W_C^T
    gemm_tf32_nt<<<grid, 256>>>(hbuf, W_C, out, MSZ, DSZ, NSZ);

    // out += D_skip * x
    skip_kernel<<<(MSZ * DSZ) / 256, 256>>>(out, x, D_skip);
}

// round 3
// speedup vs baseline: 1.3456x; 1.3456x over previous
#include <cuda_runtime.h>
#include <cstdint>
#include <math.h>

// Problem sizes (fixed): B=4, S=2048, D=N=K=2048
#define BSZ 4
#define SSZ 2048
#define DSZ 2048
#define NSZ 2048
#define KSZ 2048
#define MSZ (BSZ * SSZ)   // 8192

#define NCHUNK 16
#define CLEN (SSZ / NCHUNK)  // 128

// ---------------- GEMM tiling ----------------
#define BM 128
#define BN 128
#define BK 32
#define NKITER (KSZ / BK)       // 64
#define SSTRIDE 36              // padded floats per row -> conflict-free frag loads
#define STAGE_FLOATS (BM * SSTRIDE)          // 4608 per tile
#define SMEM_FLOATS (4 * STAGE_FLOATS)       // A0,B0,A1,B1 = 18432 floats = 72KB

// ---------------- scratch (device globals; no allocation allowed) ----------
__device__ float g_buf0[(size_t)MSZ * NSZ];   // dt_lin -> A_bar
__device__ float g_buf1[(size_t)MSZ * NSZ];   // Bp     -> inputs
__device__ float g_h[(size_t)MSZ * NSZ];      // h_all (tf32-rounded)
__device__ float g_xtf[(size_t)MSZ * KSZ];    // x rounded to tf32
__device__ float g_wtf[3 * (size_t)NSZ * KSZ];// W_dt, W_B, W_C rounded to tf32
__device__ float g_prod[BSZ * NCHUNK * NSZ];
__device__ float g_hend[BSZ * NCHUNK * NSZ];
__device__ float g_hin[BSZ * NCHUNK * NSZ];

// ---------------- helpers ----------------
__device__ __forceinline__ float totf(float f) {
    uint32_t u; asm("cvt.rna.tf32.f32 %0, %1;" : "=r"(u) : "f"(f));
    return __uint_as_float(u);
}

__device__ __forceinline__ void cp16(uint32_t s, const void* g) {
    asm volatile("cp.async.cg.shared.global [%0], [%1], 16;" :: "r"(s), "l"(g));
}

// mma.sync m16n8k8 tf32: D = A*B + D  (A row-major 16x8, B col-major 8x8)
__device__ __forceinline__ void mma8(float* d, const float* a, const float* b) {
    asm volatile(
        "mma.sync.aligned.m16n8k8.row.col.f32.tf32.tf32.f32 "
        "{%0,%1,%2,%3}, {%4,%5,%6,%7}, {%8,%9}, {%0,%1,%2,%3};"
        : "+f"(d[0]), "+f"(d[1]), "+f"(d[2]), "+f"(d[3])
        : "r"(__float_as_uint(a[0])), "r"(__float_as_uint(a[1])),
          "r"(__float_as_uint(a[2])), "r"(__float_as_uint(a[3])),
          "r"(__float_as_uint(b[0])), "r"(__float_as_uint(b[1])));
}

// ---------------------------------------------------------------------------
// tf32 mma.sync GEMM (NT): C[m][n] = sum_k A[m][k] * W[n][k]
// A: [M,K] rm, W: [N,K] rm, C: [M,2048] rm. Inputs must be tf32-pre-rounded.
// MODE 0: plain store.  MODE 1: C = acc + Dsk[n]*X[m][n]
// ---------------------------------------------------------------------------
template <int MODE>
__global__ __launch_bounds__(256) void gemm_tc(
    const float* __restrict__ A, const float* __restrict__ W,
    float* __restrict__ C, const float* __restrict__ X,
    const float* __restrict__ Dsk)
{
    extern __shared__ float smem[];
    float* sA[2] = { smem,                  smem + 2 * STAGE_FLOATS };
    float* sB[2] = { smem + STAGE_FLOATS,   smem + 3 * STAGE_FLOATS };

    const int tid = threadIdx.x;
    const int wid = tid >> 5, lane = tid & 31;
    const int m0 = blockIdx.y * BM;
    const int n0 = blockIdx.x * BN;
    // 8 warps: 2 rows (m) x 4 cols (n); warp tile 64 x 32
    const int wm = (wid >> 2) * 64;
    const int wn = (wid & 3) * 32;
    const int lr = lane >> 2;      // 0..7
    const int lc = lane & 3;       // 0..3

    const uint32_t sbase = (uint32_t)__cvta_generic_to_shared(smem);

    float acc[4][4][4];
    #pragma unroll
    for (int i = 0; i < 4; i++)
        #pragma unroll
        for (int j = 0; j < 4; j++)
            #pragma unroll
            for (int t = 0; t < 4; t++)
                acc[i][j][t] = 0.0f;

    auto load_tile = [&](int buf, int kt) {
        const float* Ap = A + (size_t)m0 * KSZ + kt * BK;
        const float* Wp = W + (size_t)n0 * KSZ + kt * BK;
        uint32_t baseA = sbase + (uint32_t)((buf ? 2 * STAGE_FLOATS : 0) * 4);
        uint32_t baseB = sbase + (uint32_t)((buf ? 3 * STAGE_FLOATS : STAGE_FLOATS) * 4);
        #pragma unroll
        for (int i = 0; i < 4; i++) {               // A: 128 rows x 8 chunks of 16B
            int idx = tid + i * 256;
            int r = idx >> 3, c = idx & 7;
            cp16(baseA + (uint32_t)(r * SSTRIDE + c * 4) * 4, Ap + (size_t)r * KSZ + c * 4);
        }
        #pragma unroll
        for (int i = 0; i < 4; i++) {               // B: 128 rows x 8 chunks
            int idx = tid + i * 256;
            int r = idx >> 3, c = idx & 7;
            cp16(baseB + (uint32_t)(r * SSTRIDE + c * 4) * 4, Wp + (size_t)r * KSZ + c * 4);
        }
        asm volatile("cp.async.commit_group;");
    };

    load_tile(0, 0);
    load_tile(1, 1);

    #pragma unroll 1
    for (int kt = 0; kt < NKITER; kt++) {
        const int cur = kt & 1;
        if (kt < NKITER - 1) asm volatile("cp.async.wait_group 1;");
        else                 asm volatile("cp.async.wait_group 0;");
        __syncthreads();

        const float* a_s = sA[cur];
        const float* b_s = sB[cur];
        #pragma unroll
        for (int kk = 0; kk < 4; kk++) {
            const int kb = kk * 8;
            float af[4][4], bf[4][2];
            #pragma unroll
            for (int mt = 0; mt < 4; mt++) {
                const float* p = a_s + (wm + mt * 16 + lr) * SSTRIDE + kb + lc;
                af[mt][0] = p[0];
                af[mt][1] = p[8 * SSTRIDE];
                af[mt][2] = p[4];
                af[mt][3] = p[8 * SSTRIDE + 4];
            }
            #pragma unroll
            for (int nt = 0; nt < 4; nt++) {
                const float* p = b_s + (wn + nt * 8 + lr) * SSTRIDE + kb + lc;
                bf[nt][0] = p[0];
                bf[nt][1] = p[4];
            }
            #pragma unroll
            for (int mt = 0; mt < 4; mt++)
                #pragma unroll
                for (int nt = 0; nt < 4; nt++)
                    mma8(acc[mt][nt], af[mt], bf[nt]);
        }
        __syncthreads();
        if (kt + 2 < NKITER) load_tile(cur, kt + 2);
    }

    // epilogue
    #pragma unroll
    for (int mt = 0; mt < 4; mt++) {
        #pragma unroll
        for (int nt = 0; nt < 4; nt++) {
            int r0 = m0 + wm + mt * 16 + lr;
            int c0 = n0 + wn + nt * 8 + lc * 2;
            float2 v0 = { acc[mt][nt][0], acc[mt][nt][1] };
            float2 v1 = { acc[mt][nt][2], acc[mt][nt][3] };
            if (MODE == 1) {
                float2 d0 = *(const float2*)(Dsk + c0);
                float2 x0 = *(const float2*)(X + (size_t)r0 * NSZ + c0);
                float2 x1 = *(const float2*)(X + (size_t)(r0 + 8) * NSZ + c0);
                v0.x += d0.x * x0.x; v0.y += d0.y * x0.y;
                v1.x += d0.x * x1.x; v1.y += d0.y * x1.y;
            }
            *(float2*)(C + (size_t)r0 * NSZ + c0) = v0;
            *(float2*)(C + (size_t)(r0 + 8) * NSZ + c0) = v1;
        }
    }
}

// ---------------------------------------------------------------------------
// Round fp32 buffer to tf32 (RN)
// ---------------------------------------------------------------------------
__global__ void round_tf32_k(const float* __restrict__ in, float* __restrict__ out)
{
    size_t i = (size_t)blockIdx.x * blockDim.x + threadIdx.x;
    float4 v = ((const float4*)in)[i];
    v.x = totf(v.x); v.y = totf(v.y); v.z = totf(v.z); v.w = totf(v.w);
    ((float4*)out)[i] = v;
}

// ---------------------------------------------------------------------------
// Elementwise: dt = softplus(dt_lin + b_dt); A_bar = exp(dt * -exp(A_log));
//              inputs = dt * Bp * x   (in place into g_buf0/g_buf1)
// ---------------------------------------------------------------------------
__global__ void elem_kernel(const float* __restrict__ x,
                            const float* __restrict__ b_dt,
                            const float* __restrict__ A_log)
{
    size_t idx = (size_t)blockIdx.x * blockDim.x + threadIdx.x;
    int n = (int)(idx & (NSZ - 1));
    float dtl = g_buf0[idx] + b_dt[n];
    float dt = (dtl > 20.0f) ? dtl : log1pf(expf(dtl));
    float Aa = -expf(A_log[n]);
    float abar = expf(dt * Aa);
    float inp = dt * g_buf1[idx] * x[idx];
    g_buf0[idx] = abar;
    g_buf1[idx] = inp;
}

// ---------------------------------------------------------------------------
// Chunked selective scan
// ---------------------------------------------------------------------------
__global__ void scan_pass1()
{
    int gid = blockIdx.x * blockDim.x + threadIdx.x;
    int n = gid & (NSZ - 1);
    int c = (gid >> 11) & (NCHUNK - 1);
    int b = gid >> 15;
    size_t base = ((size_t)(b * SSZ + c * CLEN)) * NSZ + n;
    float h = 0.0f, p = 1.0f;
    #pragma unroll 4
    for (int t = 0; t < CLEN; t++) {
        float ab = g_buf0[base];
        float u  = g_buf1[base];
        h = ab * h + u;
        p *= ab;
        base += NSZ;
    }
    g_prod[gid] = p;
    g_hend[gid] = h;
}

__global__ void scan_pass2()
{
    int gid = blockIdx.x * blockDim.x + threadIdx.x;
    int n = gid & (NSZ - 1);
    int b = gid >> 11;
    float hin = 0.0f;
    #pragma unroll
    for (int c = 0; c < NCHUNK; c++) {
        int ci = (b * NCHUNK + c) * NSZ + n;
        g_hin[ci] = hin;
        hin = g_prod[ci] * hin + g_hend[ci];
    }
}

__global__ void scan_pass3()
{
    int gid = blockIdx.x * blockDim.x + threadIdx.x;
    int n = gid & (NSZ - 1);
    int c = (gid >> 11) & (NCHUNK - 1);
    int b = gid >> 15;
    size_t base = ((size_t)(b * SSZ + c * CLEN)) * NSZ + n;
    float h = g_hin[gid];
    #pragma unroll 4
    for (int t = 0; t < CLEN; t++) {
        float ab = g_buf0[base];
        float u  = g_buf1[base];
        h = ab * h + u;
        g_h[base] = totf(h);          // tf32-round for GEMM3 A operand
        base += NSZ;
    }
}

// ---------------------------------------------------------------------------
extern "C" void kernel_launch(void* const* d_in, const int* in_sizes, int n_in,
                              void* d_out, int out_size)
{
    const float* x      = (const float*)d_in[0];
    const float* W_dt   = (const float*)d_in[1];
    const float* b_dt   = (const float*)d_in[2];
    const float* W_B    = (const float*)d_in[3];
    const float* W_C    = (const float*)d_in[4];
    const float* A_log  = (const float*)d_in[5];
    const float* D_skip = (const float*)d_in[6];
    float* out = (float*)d_out;

    float *buf0, *buf1, *hbuf, *xtf, *wtf;
    cudaGetSymbolAddress((void**)&buf0, g_buf0);
    cudaGetSymbolAddress((void**)&buf1, g_buf1);
    cudaGetSymbolAddress((void**)&hbuf, g_h);
    cudaGetSymbolAddress((void**)&xtf, g_xtf);
    cudaGetSymbolAddress((void**)&wtf, g_wtf);
    float* wdt_tf = wtf;
    float* wb_tf  = wtf + (size_t)NSZ * KSZ;
    float* wc_tf  = wtf + 2 * (size_t)NSZ * KSZ;

    const int SMEM_BYTES = SMEM_FLOATS * 4;   // 73728
    cudaFuncSetAttribute(gemm_tc<0>, cudaFuncAttributeMaxDynamicSharedMemorySize, SMEM_BYTES);
    cudaFuncSetAttribute(gemm_tc<1>, cudaFuncAttributeMaxDynamicSharedMemorySize, SMEM_BYTES);

    // tf32-round operands
    round_tf32_k<<<(MSZ * (size_t)KSZ) / 4 / 256, 256>>>(x, xtf);
    round_tf32_k<<<(NSZ * (size_t)KSZ) / 4 / 256, 256>>>(W_dt, wdt_tf);
    round_tf32_k<<<(NSZ * (size_t)KSZ) / 4 / 256, 256>>>(W_B,  wb_tf);
    round_tf32_k<<<(NSZ * (size_t)KSZ) / 4 / 256, 256>>>(W_C,  wc_tf);

    dim3 grid(NSZ / BN, MSZ / BM);   // (16, 64)

    // dt_lin = x @ W_dt^T ; Bp = x @ W_B^T
    gemm_tc<0><<<grid, 256, SMEM_BYTES>>>(xtf, wdt_tf, buf0, nullptr, nullptr);
    gemm_tc<0><<<grid, 256, SMEM_BYTES>>>(xtf, wb_tf,  buf1, nullptr, nullptr);

    // elementwise: A_bar, inputs
    elem_kernel<<<(MSZ * (size_t)NSZ) / 256, 256>>>(x, b_dt, A_log);

    // chunked selective scan
    scan_pass1<<<(BSZ * NCHUNK * NSZ) / 256, 256>>>();
    scan_pass2<<<(BSZ * NSZ) / 256, 256>>>();
    scan_pass3<<<(BSZ * NCHUNK * NSZ) / 256, 256>>>();

    // out = h @ W_C^T + D_skip * x   (skip fused in epilogue)
    gemm_tc<1><<<grid, 256, SMEM_BYTES>>>(hbuf, wc_tf, out, x, D_skip);
}

// round 4
// speedup vs baseline: 2.3309x; 1.7322x over previous
#include <cuda_runtime.h>
#include <cstdint>
#include <math.h>

// Problem sizes (fixed): B=4, S=2048, D=N=K=2048
#define BSZ 4
#define SSZ 2048
#define DSZ 2048
#define NSZ 2048
#define KSZ 2048
#define MSZ (BSZ * SSZ)   // 8192

#define NCHUNK 16
#define CLEN (SSZ / NCHUNK)  // 128

// ---------------- GEMM tiling ----------------
#define BM 128
#define BN 256
#define BK 32
#define NKITER (KSZ / BK)       // 64
#define SSTRIDE 36              // padded floats/row -> conflict-free frag loads
#define A_FLOATS (BM * SSTRIDE)             // 4608
#define B_FLOATS (BN * SSTRIDE)             // 9216
#define STAGE_FLOATS (A_FLOATS + B_FLOATS)  // 13824
#define SMEM_BYTES (2 * STAGE_FLOATS * 4)   // 110592

// ---------------- scratch (device globals; no allocation allowed) ----------
__device__ float g_buf0[(size_t)MSZ * NSZ];   // dt_lin (raw)
__device__ float g_buf1[(size_t)MSZ * NSZ];   // Bp (raw)
__device__ float g_h[(size_t)MSZ * NSZ];      // h_all (tf32-rounded)
__device__ float g_xtf[(size_t)MSZ * KSZ];    // x rounded to tf32
__device__ float g_wtf[3 * (size_t)NSZ * KSZ];// W_dt | W_B | W_C (tf32)
__device__ float g_prod[BSZ * NCHUNK * NSZ];
__device__ float g_hend[BSZ * NCHUNK * NSZ];
__device__ float g_hin[BSZ * NCHUNK * NSZ];

// ---------------- helpers ----------------
__device__ __forceinline__ float totf(float f) {
    uint32_t u; asm("cvt.rna.tf32.f32 %0, %1;" : "=r"(u) : "f"(f));
    return __uint_as_float(u);
}
__device__ __forceinline__ float ex2(float f) {
    float r; asm("ex2.approx.f32 %0, %1;" : "=f"(r) : "f"(f)); return r;
}
__device__ __forceinline__ float lg2(float f) {
    float r; asm("lg2.approx.f32 %0, %1;" : "=f"(r) : "f"(f)); return r;
}
__device__ __forceinline__ void cp16(uint32_t s, const void* g) {
    asm volatile("cp.async.cg.shared.global [%0], [%1], 16;" :: "r"(s), "l"(g));
}

// mma.sync m16n8k8 tf32: D += A*B (A rm 16x8, B cm 8x8)
__device__ __forceinline__ void mma8(float* d, const float* a, const float* b) {
    asm volatile(
        "mma.sync.aligned.m16n8k8.row.col.f32.tf32.tf32.f32 "
        "{%0,%1,%2,%3}, {%4,%5,%6,%7}, {%8,%9}, {%0,%1,%2,%3};"
        : "+f"(d[0]), "+f"(d[1]), "+f"(d[2]), "+f"(d[3])
        : "r"(__float_as_uint(a[0])), "r"(__float_as_uint(a[1])),
          "r"(__float_as_uint(a[2])), "r"(__float_as_uint(a[3])),
          "r"(__float_as_uint(b[0])), "r"(__float_as_uint(b[1])));
}

// ---------------------------------------------------------------------------
// tf32 mma.sync GEMM (NT): C[m][n] = sum_k A[m][k] * W[n][k]
// CTA 128x256, 8 warps 2x4, warp tile 64x64. 2-stage cp.async pipeline.
// MODE 0: dual-output (n0 < NSZ -> C0, else C1 at n0-NSZ), raw store.
// MODE 1: single output C0 = acc + Dsk[n]*X[m][n].
// ---------------------------------------------------------------------------
template <int MODE>
__global__ __launch_bounds__(256) void gemm_tc(
    const float* __restrict__ A, const float* __restrict__ W,
    float* __restrict__ C0, float* __restrict__ C1,
    const float* __restrict__ X, const float* __restrict__ Dsk)
{
    extern __shared__ float smem[];
    const int tid = threadIdx.x;
    const int wid = tid >> 5, lane = tid & 31;
    const int m0 = blockIdx.y * BM;
    const int n0 = blockIdx.x * BN;
    const int wm = (wid >> 2) * 64;      // 2 m-warps
    const int wn = (wid & 3) * 64;       // 4 n-warps
    const int lr = lane >> 2;            // 0..7
    const int lc = lane & 3;             // 0..3

    const uint32_t sbase = (uint32_t)__cvta_generic_to_shared(smem);

    float acc[4][8][4];
    #pragma unroll
    for (int i = 0; i < 4; i++)
        #pragma unroll
        for (int j = 0; j < 8; j++) {
            acc[i][j][0] = 0.f; acc[i][j][1] = 0.f;
            acc[i][j][2] = 0.f; acc[i][j][3] = 0.f;
        }

    auto load_tile = [&](int buf, int kt) {
        const float* Ap = A + (size_t)m0 * KSZ + kt * BK;
        const float* Wp = W + (size_t)n0 * KSZ + kt * BK;
        uint32_t baseA = sbase + (uint32_t)(buf * STAGE_FLOATS) * 4u;
        uint32_t baseB = baseA + (uint32_t)A_FLOATS * 4u;
        #pragma unroll
        for (int i = 0; i < 4; i++) {               // A: 128 rows x 8 x 16B
            int idx = tid + i * 256;
            int r = idx >> 3, c = idx & 7;
            cp16(baseA + (uint32_t)(r * SSTRIDE + c * 4) * 4u,
                 Ap + (size_t)r * KSZ + c * 4);
        }
        #pragma unroll
        for (int i = 0; i < 8; i++) {               // B: 256 rows x 8 x 16B
            int idx = tid + i * 256;
            int r = idx >> 3, c = idx & 7;
            cp16(baseB + (uint32_t)(r * SSTRIDE + c * 4) * 4u,
                 Wp + (size_t)r * KSZ + c * 4);
        }
        asm volatile("cp.async.commit_group;");
    };

    load_tile(0, 0);
    load_tile(1, 1);

    #pragma unroll 1
    for (int kt = 0; kt < NKITER; kt++) {
        const int cur = kt & 1;
        if (kt < NKITER - 1) asm volatile("cp.async.wait_group 1;");
        else                 asm volatile("cp.async.wait_group 0;");
        __syncthreads();

        const float* a_s = smem + cur * STAGE_FLOATS;
        const float* b_s = a_s + A_FLOATS;
        #pragma unroll
        for (int kk = 0; kk < 4; kk++) {
            const int kb = kk * 8;
            float af[4][4], bf[8][2];
            #pragma unroll
            for (int mt = 0; mt < 4; mt++) {
                const float* p = a_s + (wm + mt * 16 + lr) * SSTRIDE + kb + lc;
                af[mt][0] = p[0];
                af[mt][1] = p[8 * SSTRIDE];
                af[mt][2] = p[4];
                af[mt][3] = p[8 * SSTRIDE + 4];
            }
            #pragma unroll
            for (int nt = 0; nt < 8; nt++) {
                const float* p = b_s + (wn + nt * 8 + lr) * SSTRIDE + kb + lc;
                bf[nt][0] = p[0];
                bf[nt][1] = p[4];
            }
            #pragma unroll
            for (int mt = 0; mt < 4; mt++)
                #pragma unroll
                for (int nt = 0; nt < 8; nt++)
                    mma8(acc[mt][nt], af[mt], bf[nt]);
        }
        __syncthreads();
        if (kt + 2 < NKITER) load_tile(cur, kt + 2);
    }

    // epilogue
    float* Cw = C0;
    int ncol = n0;
    if (MODE == 0 && n0 >= NSZ) { Cw = C1; ncol = n0 - NSZ; }

    #pragma unroll
    for (int mt = 0; mt < 4; mt++) {
        #pragma unroll
        for (int nt = 0; nt < 8; nt++) {
            int r0 = m0 + wm + mt * 16 + lr;
            int c0 = ncol + wn + nt * 8 + lc * 2;
            float2 v0 = { acc[mt][nt][0], acc[mt][nt][1] };
            float2 v1 = { acc[mt][nt][2], acc[mt][nt][3] };
            if (MODE == 1) {
                float2 d0 = *(const float2*)(Dsk + c0);
                float2 x0 = *(const float2*)(X + (size_t)r0 * NSZ + c0);
                float2 x1 = *(const float2*)(X + (size_t)(r0 + 8) * NSZ + c0);
                v0.x += d0.x * x0.x; v0.y += d0.y * x0.y;
                v1.x += d0.x * x1.x; v1.y += d0.y * x1.y;
            }
            *(float2*)(Cw + (size_t)r0 * NSZ + c0) = v0;
            *(float2*)(Cw + (size_t)(r0 + 8) * NSZ + c0) = v1;
        }
    }
}

// ---------------------------------------------------------------------------
// Round fp32 buffer to tf32 (RN)
// ---------------------------------------------------------------------------
__global__ void round_tf32_k(const float* __restrict__ in, float* __restrict__ out)
{
    size_t i = (size_t)blockIdx.x * blockDim.x + threadIdx.x;
    float4 v = ((const float4*)in)[i];
    v.x = totf(v.x); v.y = totf(v.y); v.z = totf(v.z); v.w = totf(v.w);
    ((float4*)out)[i] = v;
}

// ---------------------------------------------------------------------------
// Fused transform: from raw dt_lin (buf0), Bp (buf1), x:
//   z = dt_lin + b_dt[n];  L = log2(1+2^(z*log2e))  (or z*log2e if large)
//   dt = L*ln2;  abar = 2^(L*Aa),  Aa = -exp(A_log[n]);  inp = dt*Bp*x
// ---------------------------------------------------------------------------
__device__ __forceinline__ void transform(float dtl, float bp, float xv,
                                          float bd, float Aa,
                                          float& abar, float& inp)
{
    float z = dtl + bd;
    float e = ex2(z * 1.442695041f);
    float L = (z > 15.0f) ? z * 1.442695041f : lg2(1.0f + e);
    abar = ex2(L * Aa);
    float dt = L * 0.69314718056f;
    inp = dt * bp * xv;
}

// ---------------------------------------------------------------------------
// Chunked selective scan (transform fused into pass1 & pass3)
// ---------------------------------------------------------------------------
__global__ void scan_pass1(const float* __restrict__ x,
                           const float* __restrict__ b_dt,
                           const float* __restrict__ A_log)
{
    int gid = blockIdx.x * blockDim.x + threadIdx.x;
    int n = gid & (NSZ - 1);
    int c = (gid >> 11) & (NCHUNK - 1);
    int b = gid >> 15;
    float bd = b_dt[n];
    float Aa = -expf(A_log[n]);
    size_t base = ((size_t)(b * SSZ + c * CLEN)) * NSZ + n;
    float h = 0.0f, p = 1.0f;
    #pragma unroll 4
    for (int t = 0; t < CLEN; t++) {
        float abar, inp;
        transform(g_buf0[base], g_buf1[base], x[base], bd, Aa, abar, inp);
        h = abar * h + inp;
        p *= abar;
        base += NSZ;
    }
    g_prod[gid] = p;
    g_hend[gid] = h;
}

__global__ void scan_pass2()
{
    int gid = blockIdx.x * blockDim.x + threadIdx.x;
    int n = gid & (NSZ - 1);
    int b = gid >> 11;
    float hin = 0.0f;
    #pragma unroll
    for (int c = 0; c < NCHUNK; c++) {
        int ci = (b * NCHUNK + c) * NSZ + n;
        g_hin[ci] = hin;
        hin = g_prod[ci] * hin + g_hend[ci];
    }
}

__global__ void scan_pass3(const float* __restrict__ x,
                           const float* __restrict__ b_dt,
                           const float* __restrict__ A_log)
{
    int gid = blockIdx.x * blockDim.x + threadIdx.x;
    int n = gid & (NSZ - 1);
    int c = (gid >> 11) & (NCHUNK - 1);
    int b = gid >> 15;
    float bd = b_dt[n];
    float Aa = -expf(A_log[n]);
    size_t base = ((size_t)(b * SSZ + c * CLEN)) * NSZ + n;
    float h = g_hin[gid];
    #pragma unroll 4
    for (int t = 0; t < CLEN; t++) {
        float abar, inp;
        transform(g_buf0[base], g_buf1[base], x[base], bd, Aa, abar, inp);
        h = abar * h + inp;
        g_h[base] = totf(h);          // tf32-round for GEMM3 A operand
        base += NSZ;
    }
}

// ---------------------------------------------------------------------------
extern "C" void kernel_launch(void* const* d_in, const int* in_sizes, int n_in,
                              void* d_out, int out_size)
{
    const float* x      = (const float*)d_in[0];
    const float* W_dt   = (const float*)d_in[1];
    const float* b_dt   = (const float*)d_in[2];
    const float* W_B    = (const float*)d_in[3];
    const float* W_C    = (const float*)d_in[4];
    const float* A_log  = (const float*)d_in[5];
    const float* D_skip = (const float*)d_in[6];
    float* out = (float*)d_out;

    float *buf0, *buf1, *hbuf, *xtf, *wtf;
    cudaGetSymbolAddress((void**)&buf0, g_buf0);
    cudaGetSymbolAddress((void**)&buf1, g_buf1);
    cudaGetSymbolAddress((void**)&hbuf, g_h);
    cudaGetSymbolAddress((void**)&xtf, g_xtf);
    cudaGetSymbolAddress((void**)&wtf, g_wtf);
    float* wc_tf = wtf + 2 * (size_t)NSZ * KSZ;

    cudaFuncSetAttribute(gemm_tc<0>, cudaFuncAttributeMaxDynamicSharedMemorySize, SMEM_BYTES);
    cudaFuncSetAttribute(gemm_tc<1>, cudaFuncAttributeMaxDynamicSharedMemorySize, SMEM_BYTES);

    // tf32-round operands (W_dt and W_B land contiguously -> stacked N=4096)
    round_tf32_k<<<(MSZ * (size_t)KSZ) / 4 / 256, 256>>>(x, xtf);
    round_tf32_k<<<(NSZ * (size_t)KSZ) / 4 / 256, 256>>>(W_dt, wtf);
    round_tf32_k<<<(NSZ * (size_t)KSZ) / 4 / 256, 256>>>(W_B,  wtf + (size_t)NSZ * KSZ);
    round_tf32_k<<<(NSZ * (size_t)KSZ) / 4 / 256, 256>>>(W_C,  wc_tf);

    // dt_lin & Bp in ONE GEMM over stacked N=4096
    dim3 grid12(2 * NSZ / BN, MSZ / BM);   // (16, 64)
    gemm_tc<0><<<grid12, 256, SMEM_BYTES>>>(xtf, wtf, buf0, buf1, nullptr, nullptr);

    // fused transform + chunked selective scan
    scan_pass1<<<(BSZ * NCHUNK * NSZ) / 256, 256>>>(x, b_dt, A_log);
    scan_pass2<<<(BSZ * NSZ) / 256, 256>>>();
    scan_pass3<<<(BSZ * NCHUNK * NSZ) / 256, 256>>>(x, b_dt, A_log);

    // out = h @ W_C^T + D_skip * x   (skip fused in epilogue)
    dim3 grid3(NSZ / BN, MSZ / BM);        // (8, 64)
    gemm_tc<1><<<grid3, 256, SMEM_BYTES>>>(hbuf, wc_tf, out, nullptr, x, D_skip);
}

// round 5
// speedup vs baseline: 2.4040x; 1.0314x over previous
#include <cuda_runtime.h>
#include <cstdint>
#include <math.h>

// Problem sizes (fixed): B=4, S=2048, D=N=K=2048
#define BSZ 4
#define SSZ 2048
#define DSZ 2048
#define NSZ 2048
#define KSZ 2048
#define MSZ (BSZ * SSZ)   // 8192

#define NCHUNK 16
#define CLEN (SSZ / NCHUNK)  // 128

// ---------------- GEMM tiling ----------------
#define BM 128
#define BN 128
#define BK 32
#define NKITER (KSZ / BK)       // 64
#define NSTAGE 3
#define SSTRIDE 36              // padded floats/row -> conflict-free frag loads
#define A_FLOATS (BM * SSTRIDE)             // 4608
#define B_FLOATS (BN * SSTRIDE)             // 4608
#define STAGE_FLOATS (A_FLOATS + B_FLOATS)  // 9216
#define SMEM_BYTES (NSTAGE * STAGE_FLOATS * 4)   // 110592 (108KB)

// ---------------- scratch (device globals; no allocation allowed) ----------
__device__ float g_buf0[(size_t)MSZ * NSZ];   // dt_lin (raw)
__device__ float g_buf1[(size_t)MSZ * NSZ];   // Bp (raw)
__device__ float g_h[(size_t)MSZ * NSZ];      // h_all (tf32-rounded)
__device__ float g_xtf[(size_t)MSZ * KSZ];    // x rounded to tf32
__device__ float g_wtf[3 * (size_t)NSZ * KSZ];// W_dt | W_B | W_C (tf32)
__device__ float g_prod[BSZ * NCHUNK * NSZ];
__device__ float g_hend[BSZ * NCHUNK * NSZ];
__device__ float g_hin[BSZ * NCHUNK * NSZ];

// ---------------- helpers ----------------
__device__ __forceinline__ float totf(float f) {
    uint32_t u; asm("cvt.rna.tf32.f32 %0, %1;" : "=r"(u) : "f"(f));
    return __uint_as_float(u);
}
__device__ __forceinline__ float ex2(float f) {
    float r; asm("ex2.approx.f32 %0, %1;" : "=f"(r) : "f"(f)); return r;
}
__device__ __forceinline__ float lg2(float f) {
    float r; asm("lg2.approx.f32 %0, %1;" : "=f"(r) : "f"(f)); return r;
}
__device__ __forceinline__ void cp16(uint32_t s, const void* g) {
    asm volatile("cp.async.cg.shared.global [%0], [%1], 16;" :: "r"(s), "l"(g));
}

// mma.sync m16n8k8 tf32: D += A*B (A rm 16x8, B cm 8x8)
__device__ __forceinline__ void mma8(float* d, const float* a, const float* b) {
    asm volatile(
        "mma.sync.aligned.m16n8k8.row.col.f32.tf32.tf32.f32 "
        "{%0,%1,%2,%3}, {%4,%5,%6,%7}, {%8,%9}, {%0,%1,%2,%3};"
        : "+f"(d[0]), "+f"(d[1]), "+f"(d[2]), "+f"(d[3])
        : "r"(__float_as_uint(a[0])), "r"(__float_as_uint(a[1])),
          "r"(__float_as_uint(a[2])), "r"(__float_as_uint(a[3])),
          "r"(__float_as_uint(b[0])), "r"(__float_as_uint(b[1])));
}

// ---------------------------------------------------------------------------
// tf32 mma.sync GEMM (NT): C[m][n] = sum_k A[m][k] * W[n][k]
// CTA 128x128, 4 warps (2x2), warp tile 64x64. 3-stage cp.async pipeline,
// ONE __syncthreads per iteration. 2 CTAs/SM.
// MODE 0: dual-output (n0 < NSZ -> C0, else C1 at n0-NSZ), raw store.
// MODE 1: single output C0 = acc + Dsk[n]*X[m][n].
// ---------------------------------------------------------------------------
template <int MODE>
__global__ __launch_bounds__(128, 2) void gemm_tc(
    const float* __restrict__ A, const float* __restrict__ W,
    float* __restrict__ C0, float* __restrict__ C1,
    const float* __restrict__ X, const float* __restrict__ Dsk)
{
    extern __shared__ float smem[];
    const int tid = threadIdx.x;
    const int wid = tid >> 5, lane = tid & 31;
    const int m0 = blockIdx.y * BM;
    const int n0 = blockIdx.x * BN;
    const int wm = (wid >> 1) * 64;      // 2 m-warps
    const int wn = (wid & 1) * 64;       // 2 n-warps
    const int lr = lane >> 2;            // 0..7
    const int lc = lane & 3;             // 0..3

    const uint32_t sbase = (uint32_t)__cvta_generic_to_shared(smem);

    float acc[4][8][4];
    #pragma unroll
    for (int i = 0; i < 4; i++)
        #pragma unroll
        for (int j = 0; j < 8; j++) {
            acc[i][j][0] = 0.f; acc[i][j][1] = 0.f;
            acc[i][j][2] = 0.f; acc[i][j][3] = 0.f;
        }

    auto load_tile = [&](int stage, int kt) {
        const float* Ap = A + (size_t)m0 * KSZ + kt * BK;
        const float* Wp = W + (size_t)n0 * KSZ + kt * BK;
        uint32_t baseA = sbase + (uint32_t)(stage * STAGE_FLOATS) * 4u;
        uint32_t baseB = baseA + (uint32_t)A_FLOATS * 4u;
        #pragma unroll
        for (int i = 0; i < 8; i++) {               // A: 128 rows x 8 x 16B
            int idx = tid + i * 128;
            int r = idx >> 3, c = idx & 7;
            cp16(baseA + (uint32_t)(r * SSTRIDE + c * 4) * 4u,
                 Ap + (size_t)r * KSZ + c * 4);
        }
        #pragma unroll
        for (int i = 0; i < 8; i++) {               // B: 128 rows x 8 x 16B
            int idx = tid + i * 128;
            int r = idx >> 3, c = idx & 7;
            cp16(baseB + (uint32_t)(r * SSTRIDE + c * 4) * 4u,
                 Wp + (size_t)r * KSZ + c * 4);
        }
        asm volatile("cp.async.commit_group;");
    };

    load_tile(0, 0);
    load_tile(1, 1);

    #pragma unroll 1
    for (int kt = 0; kt < NKITER; kt++) {
        const int cur = kt % NSTAGE;
        if (kt < NKITER - 1) asm volatile("cp.async.wait_group 1;");
        else                 asm volatile("cp.async.wait_group 0;");
        __syncthreads();
        // prefetch stage kt+2 (overwrites stage consumed at kt-1; safe after sync)
        if (kt + 2 < NKITER) load_tile((kt + 2) % NSTAGE, kt + 2);

        const float* a_s = smem + cur * STAGE_FLOATS;
        const float* b_s = a_s + A_FLOATS;
        #pragma unroll
        for (int kk = 0; kk < 4; kk++) {
            const int kb = kk * 8;
            float af[4][4], bf[8][2];
            #pragma unroll
            for (int mt = 0; mt < 4; mt++) {
                const float* p = a_s + (wm + mt * 16 + lr) * SSTRIDE + kb + lc;
                af[mt][0] = p[0];
                af[mt][1] = p[8 * SSTRIDE];
                af[mt][2] = p[4];
                af[mt][3] = p[8 * SSTRIDE + 4];
            }
            #pragma unroll
            for (int nt = 0; nt < 8; nt++) {
                const float* p = b_s + (wn + nt * 8 + lr) * SSTRIDE + kb + lc;
                bf[nt][0] = p[0];
                bf[nt][1] = p[4];
            }
            #pragma unroll
            for (int mt = 0; mt < 4; mt++)
                #pragma unroll
                for (int nt = 0; nt < 8; nt++)
                    mma8(acc[mt][nt], af[mt], bf[nt]);
        }
    }

    // epilogue
    float* Cw = C0;
    int ncol = n0;
    if (MODE == 0 && n0 >= NSZ) { Cw = C1; ncol = n0 - NSZ; }

    #pragma unroll
    for (int mt = 0; mt < 4; mt++) {
        #pragma unroll
        for (int nt = 0; nt < 8; nt++) {
            int r0 = m0 + wm + mt * 16 + lr;
            int c0 = ncol + wn + nt * 8 + lc * 2;
            float2 v0 = { acc[mt][nt][0], acc[mt][nt][1] };
            float2 v1 = { acc[mt][nt][2], acc[mt][nt][3] };
            if (MODE == 1) {
                float2 d0 = *(const float2*)(Dsk + c0);
                float2 x0 = *(const float2*)(X + (size_t)r0 * NSZ + c0);
                float2 x1 = *(const float2*)(X + (size_t)(r0 + 8) * NSZ + c0);
                v0.x += d0.x * x0.x; v0.y += d0.y * x0.y;
                v1.x += d0.x * x1.x; v1.y += d0.y * x1.y;
            }
            *(float2*)(Cw + (size_t)r0 * NSZ + c0) = v0;
            *(float2*)(Cw + (size_t)(r0 + 8) * NSZ + c0) = v1;
        }
    }
}

// ---------------------------------------------------------------------------
// Round fp32 buffer to tf32 (RN)
// ---------------------------------------------------------------------------
__global__ void round_tf32_k(const float* __restrict__ in, float* __restrict__ out)
{
    size_t i = (size_t)blockIdx.x * blockDim.x + threadIdx.x;
    float4 v = ((const float4*)in)[i];
    v.x = totf(v.x); v.y = totf(v.y); v.z = totf(v.z); v.w = totf(v.w);
    ((float4*)out)[i] = v;
}

// ---------------------------------------------------------------------------
// Fused transform: from raw dt_lin (buf0), Bp (buf1), x:
//   z = dt_lin + b_dt[n];  L = log2(1+2^(z*log2e))  (or z*log2e if large)
//   dt = L*ln2;  abar = 2^(L*Aa),  Aa = -exp(A_log[n]);  inp = dt*Bp*x
// ---------------------------------------------------------------------------
__device__ __forceinline__ void transform(float dtl, float bp, float xv,
                                          float bd, float Aa,
                                          float& abar, float& inp)
{
    float z = dtl + bd;
    float e = ex2(z * 1.442695041f);
    float L = (z > 15.0f) ? z * 1.442695041f : lg2(1.0f + e);
    abar = ex2(L * Aa);
    float dt = L * 0.69314718056f;
    inp = dt * bp * xv;
}

// ---------------------------------------------------------------------------
// Chunked selective scan (transform fused into pass1 & pass3)
// ---------------------------------------------------------------------------
__global__ void scan_pass1(const float* __restrict__ x,
                           const float* __restrict__ b_dt,
                           const float* __restrict__ A_log)
{
    int gid = blockIdx.x * blockDim.x + threadIdx.x;
    int n = gid & (NSZ - 1);
    int c = (gid >> 11) & (NCHUNK - 1);
    int b = gid >> 15;
    float bd = b_dt[n];
    float Aa = -expf(A_log[n]);
    size_t base = ((size_t)(b * SSZ + c * CLEN)) * NSZ + n;
    float h = 0.0f, p = 1.0f;
    #pragma unroll 4
    for (int t = 0; t < CLEN; t++) {
        float abar, inp;
        transform(g_buf0[base], g_buf1[base], x[base], bd, Aa, abar, inp);
        h = abar * h + inp;
        p *= abar;
        base += NSZ;
    }
    g_prod[gid] = p;
    g_hend[gid] = h;
}

__global__ void scan_pass2()
{
    int gid = blockIdx.x * blockDim.x + threadIdx.x;
    int n = gid & (NSZ - 1);
    int b = gid >> 11;
    float hin = 0.0f;
    #pragma unroll
    for (int c = 0; c < NCHUNK; c++) {
        int ci = (b * NCHUNK + c) * NSZ + n;
        g_hin[ci] = hin;
        hin = g_prod[ci] * hin + g_hend[ci];
    }
}

__global__ void scan_pass3(const float* __restrict__ x,
                           const float* __restrict__ b_dt,
                           const float* __restrict__ A_log)
{
    int gid = blockIdx.x * blockDim.x + threadIdx.x;
    int n = gid & (NSZ - 1);
    int c = (gid >> 11) & (NCHUNK - 1);
    int b = gid >> 15;
    float bd = b_dt[n];
    float Aa = -expf(A_log[n]);
    size_t base = ((size_t)(b * SSZ + c * CLEN)) * NSZ + n;
    float h = g_hin[gid];
    #pragma unroll 4
    for (int t = 0; t < CLEN; t++) {
        float abar, inp;
        transform(g_buf0[base], g_buf1[base], x[base], bd, Aa, abar, inp);
        h = abar * h + inp;
        g_h[base] = totf(h);          // tf32-round for GEMM3 A operand
        base += NSZ;
    }
}

// ---------------------------------------------------------------------------
extern "C" void kernel_launch(void* const* d_in, const int* in_sizes, int n_in,
                              void* d_out, int out_size)
{
    const float* x      = (const float*)d_in[0];
    const float* W_dt   = (const float*)d_in[1];
    const float* b_dt   = (const float*)d_in[2];
    const float* W_B    = (const float*)d_in[3];
    const float* W_C    = (const float*)d_in[4];
    const float* A_log  = (const float*)d_in[5];
    const float* D_skip = (const float*)d_in[6];
    float* out = (float*)d_out;

    float *buf0, *buf1, *hbuf, *xtf, *wtf;
    cudaGetSymbolAddress((void**)&buf0, g_buf0);
    cudaGetSymbolAddress((void**)&buf1, g_buf1);
    cudaGetSymbolAddress((void**)&hbuf, g_h);
    cudaGetSymbolAddress((void**)&xtf, g_xtf);
    cudaGetSymbolAddress((void**)&wtf, g_wtf);
    float* wc_tf = wtf + 2 * (size_t)NSZ * KSZ;

    cudaFuncSetAttribute(gemm_tc<0>, cudaFuncAttributeMaxDynamicSharedMemorySize, SMEM_BYTES);
    cudaFuncSetAttribute(gemm_tc<1>, cudaFuncAttributeMaxDynamicSharedMemorySize, SMEM_BYTES);

    // tf32-round operands (W_dt and W_B land contiguously -> stacked N=4096)
    round_tf32_k<<<(MSZ * (size_t)KSZ) / 4 / 256, 256>>>(x, xtf);
    round_tf32_k<<<(NSZ * (size_t)KSZ) / 4 / 256, 256>>>(W_dt, wtf);
    round_tf32_k<<<(NSZ * (size_t)KSZ) / 4 / 256, 256>>>(W_B,  wtf + (size_t)NSZ * KSZ);
    round_tf32_k<<<(NSZ * (size_t)KSZ) / 4 / 256, 256>>>(W_C,  wc_tf);

    // dt_lin & Bp in ONE GEMM over stacked N=4096
    dim3 grid12(2 * NSZ / BN, MSZ / BM);   // (32, 64)
    gemm_tc<0><<<grid12, 128, SMEM_BYTES>>>(xtf, wtf, buf0, buf1, nullptr, nullptr);

    // fused transform + chunked selective scan
    scan_pass1<<<(BSZ * NCHUNK * NSZ) / 256, 256>>>(x, b_dt, A_log);
    scan_pass2<<<(BSZ * NSZ) / 256, 256>>>();
    scan_pass3<<<(BSZ * NCHUNK * NSZ) / 256, 256>>>(x, b_dt, A_log);

    // out = h @ W_C^T + D_skip * x   (skip fused in epilogue)
    dim3 grid3(NSZ / BN, MSZ / BM);        // (16, 64)
    gemm_tc<1><<<grid3, 128, SMEM_BYTES>>>(hbuf, wc_tf, out, nullptr, x, D_skip);
}

// round 6
// speedup vs baseline: 4.1905x; 1.7432x over previous
#include <cuda_runtime.h>
#include <cuda_fp16.h>
#include <cstdint>
#include <math.h>

// Problem sizes (fixed): B=4, S=2048, D=N=K=2048
#define BSZ 4
#define SSZ 2048
#define DSZ 2048
#define NSZ 2048
#define KSZ 2048
#define MSZ (BSZ * SSZ)   // 8192

#define NCHUNK 16
#define CLEN (SSZ / NCHUNK)  // 128

// ---------------- GEMM tiling (fp16 mma m16n8k16) ----------------
#define BM 128
#define BN 128
#define BK 64                   // halves; 64*2B = 128B per row
#define NKITER (KSZ / BK)       // 32
#define NSTAGE 3
#define SSTR_H 72               // halves per smem row (36 words -> conflict-free)
#define A_BYTES (BM * SSTR_H * 2)            // 18432
#define B_BYTES (BN * SSTR_H * 2)            // 18432
#define STAGE_BYTES (A_BYTES + B_BYTES)      // 36864
#define SMEM_BYTES (NSTAGE * STAGE_BYTES)    // 110592 (108KB)

// ---------------- scratch (device globals; no allocation allowed) ----------
__device__ float  g_buf0[(size_t)MSZ * NSZ];   // dt_lin (raw fp32)
__device__ float  g_buf1[(size_t)MSZ * NSZ];   // Bp (raw fp32)
__device__ __half g_hh[(size_t)MSZ * NSZ];     // h_all (fp16 for GEMM3)
__device__ __half g_xh[(size_t)MSZ * KSZ];     // x in fp16
__device__ __half g_wh[3 * (size_t)NSZ * KSZ]; // W_dt | W_B | W_C in fp16
__device__ float  g_prod[BSZ * NCHUNK * NSZ];
__device__ float  g_hend[BSZ * NCHUNK * NSZ];
__device__ float  g_hin[BSZ * NCHUNK * NSZ];

// ---------------- helpers ----------------
__device__ __forceinline__ float ex2(float f) {
    float r; asm("ex2.approx.f32 %0, %1;" : "=f"(r) : "f"(f)); return r;
}
__device__ __forceinline__ float lg2(float f) {
    float r; asm("lg2.approx.f32 %0, %1;" : "=f"(r) : "f"(f)); return r;
}
__device__ __forceinline__ void cp16(uint32_t s, const void* g) {
    asm volatile("cp.async.cg.shared.global [%0], [%1], 16;" :: "r"(s), "l"(g));
}

// mma.sync m16n8k16 fp16 -> fp32 acc: D += A*B (A rm 16x16, B cm 16x8)
__device__ __forceinline__ void mma16(float* d, const uint32_t* a, const uint32_t* b) {
    asm volatile(
        "mma.sync.aligned.m16n8k16.row.col.f32.f16.f16.f32 "
        "{%0,%1,%2,%3}, {%4,%5,%6,%7}, {%8,%9}, {%0,%1,%2,%3};"
        : "+f"(d[0]), "+f"(d[1]), "+f"(d[2]), "+f"(d[3])
        : "r"(a[0]), "r"(a[1]), "r"(a[2]), "r"(a[3]), "r"(b[0]), "r"(b[1]));
}

// ---------------------------------------------------------------------------
// fp16 mma.sync GEMM (NT): C[m][n] = sum_k A[m][k] * W[n][k], fp32 accumulate
// CTA 128x128, 4 warps (2x2), warp tile 64x64, BK=64, 3-stage cp.async.
// MODE 0: dual-output (n0 < NSZ -> C0, else C1 at n0-NSZ), raw store.
// MODE 1: single output C0 = acc + Dsk[n]*X[m][n].
// ---------------------------------------------------------------------------
template <int MODE>
__global__ __launch_bounds__(128, 2) void gemm_tc(
    const __half* __restrict__ A, const __half* __restrict__ W,
    float* __restrict__ C0, float* __restrict__ C1,
    const float* __restrict__ X, const float* __restrict__ Dsk)
{
    extern __shared__ __half smem[];
    const int tid = threadIdx.x;
    const int wid = tid >> 5, lane = tid & 31;
    const int m0 = blockIdx.y * BM;
    const int n0 = blockIdx.x * BN;
    const int wm = (wid >> 1) * 64;      // 2 m-warps
    const int wn = (wid & 1) * 64;       // 2 n-warps
    const int lr = lane >> 2;            // 0..7
    const int lc = lane & 3;             // 0..3

    const uint32_t sbase = (uint32_t)__cvta_generic_to_shared(smem);

    float acc[4][8][4];
    #pragma unroll
    for (int i = 0; i < 4; i++)
        #pragma unroll
        for (int j = 0; j < 8; j++) {
            acc[i][j][0] = 0.f; acc[i][j][1] = 0.f;
            acc[i][j][2] = 0.f; acc[i][j][3] = 0.f;
        }

    auto load_tile = [&](int stage, int kt) {
        const __half* Ap = A + (size_t)m0 * KSZ + kt * BK;
        const __half* Wp = W + (size_t)n0 * KSZ + kt * BK;
        uint32_t baseA = sbase + (uint32_t)(stage * STAGE_BYTES);
        uint32_t baseB = baseA + (uint32_t)A_BYTES;
        #pragma unroll
        for (int i = 0; i < 8; i++) {               // A: 128 rows x 8 x 16B
            int idx = tid + i * 128;
            int r = idx >> 3, c = idx & 7;
            cp16(baseA + (uint32_t)(r * (SSTR_H * 2) + c * 16),
                 Ap + (size_t)r * KSZ + c * 8);
        }
        #pragma unroll
        for (int i = 0; i < 8; i++) {               // B: 128 rows x 8 x 16B
            int idx = tid + i * 128;
            int r = idx >> 3, c = idx & 7;
            cp16(baseB + (uint32_t)(r * (SSTR_H * 2) + c * 16),
                 Wp + (size_t)r * KSZ + c * 8);
        }
        asm volatile("cp.async.commit_group;");
    };

    load_tile(0, 0);
    load_tile(1, 1);

    #pragma unroll 1
    for (int kt = 0; kt < NKITER; kt++) {
        const int cur = kt % NSTAGE;
        if (kt < NKITER - 1) asm volatile("cp.async.wait_group 1;");
        else                 asm volatile("cp.async.wait_group 0;");
        __syncthreads();
        // prefetch stage kt+2 (overwrites stage consumed at kt-1; safe after sync)
        if (kt + 2 < NKITER) load_tile((kt + 2) % NSTAGE, kt + 2);

        const __half* a_s = smem + (size_t)cur * (STAGE_BYTES / 2);
        const __half* b_s = a_s + A_BYTES / 2;
        #pragma unroll
        for (int kk = 0; kk < 4; kk++) {
            const int kb = kk * 16;
            uint32_t af[4][4], bf[8][2];
            #pragma unroll
            for (int mt = 0; mt < 4; mt++) {
                const __half* p = a_s + (wm + mt * 16 + lr) * SSTR_H + kb + lc * 2;
                af[mt][0] = *(const uint32_t*)(p);
                af[mt][1] = *(const uint32_t*)(p + 8 * SSTR_H);
                af[mt][2] = *(const uint32_t*)(p + 8);
                af[mt][3] = *(const uint32_t*)(p + 8 * SSTR_H + 8);
            }
            #pragma unroll
            for (int nt = 0; nt < 8; nt++) {
                const __half* p = b_s + (wn + nt * 8 + lr) * SSTR_H + kb + lc * 2;
                bf[nt][0] = *(const uint32_t*)(p);
                bf[nt][1] = *(const uint32_t*)(p + 8);
            }
            #pragma unroll
            for (int mt = 0; mt < 4; mt++)
                #pragma unroll
                for (int nt = 0; nt < 8; nt++)
                    mma16(acc[mt][nt], af[mt], bf[nt]);
        }
    }

    // epilogue
    float* Cw = C0;
    int ncol = n0;
    if (MODE == 0 && n0 >= NSZ) { Cw = C1; ncol = n0 - NSZ; }

    #pragma unroll
    for (int mt = 0; mt < 4; mt++) {
        #pragma unroll
        for (int nt = 0; nt < 8; nt++) {
            int r0 = m0 + wm + mt * 16 + lr;
            int c0 = ncol + wn + nt * 8 + lc * 2;
            float2 v0 = { acc[mt][nt][0], acc[mt][nt][1] };
            float2 v1 = { acc[mt][nt][2], acc[mt][nt][3] };
            if (MODE == 1) {
                float2 d0 = *(const float2*)(Dsk + c0);
                float2 x0 = *(const float2*)(X + (size_t)r0 * NSZ + c0);
                float2 x1 = *(const float2*)(X + (size_t)(r0 + 8) * NSZ + c0);
                v0.x += d0.x * x0.x; v0.y += d0.y * x0.y;
                v1.x += d0.x * x1.x; v1.y += d0.y * x1.y;
            }
            *(float2*)(Cw + (size_t)r0 * NSZ + c0) = v0;
            *(float2*)(Cw + (size_t)(r0 + 8) * NSZ + c0) = v1;
        }
    }
}

// ---------------------------------------------------------------------------
// Convert fp32 buffer to fp16
// ---------------------------------------------------------------------------
__global__ void tohalf_k(const float* __restrict__ in, __half* __restrict__ out)
{
    size_t i = (size_t)blockIdx.x * blockDim.x + threadIdx.x;
    float4 v = ((const float4*)in)[i];
    __half2 h0 = __floats2half2_rn(v.x, v.y);
    __half2 h1 = __floats2half2_rn(v.z, v.w);
    ((__half2*)out)[2 * i]     = h0;
    ((__half2*)out)[2 * i + 1] = h1;
}

// ---------------------------------------------------------------------------
// Fused transform: from raw dt_lin (buf0), Bp (buf1), x:
//   z = dt_lin + b_dt[n];  L = log2(1+2^(z*log2e))  (or z*log2e if large)
//   dt = L*ln2;  abar = 2^(L*Aa),  Aa = -exp(A_log[n]);  inp = dt*Bp*x
// ---------------------------------------------------------------------------
__device__ __forceinline__ void transform(float dtl, float bp, float xv,
                                          float bd, float Aa,
                                          float& abar, float& inp)
{
    float z = dtl + bd;
    float e = ex2(z * 1.442695041f);
    float L = (z > 15.0f) ? z * 1.442695041f : lg2(1.0f + e);
    abar = ex2(L * Aa);
    float dt = L * 0.69314718056f;
    inp = dt * bp * xv;
}

// ---------------------------------------------------------------------------
// Chunked selective scan (transform fused into pass1 & pass3)
// ---------------------------------------------------------------------------
__global__ void scan_pass1(const float* __restrict__ x,
                           const float* __restrict__ b_dt,
                           const float* __restrict__ A_log)
{
    int gid = blockIdx.x * blockDim.x + threadIdx.x;
    int n = gid & (NSZ - 1);
    int c = (gid >> 11) & (NCHUNK - 1);
    int b = gid >> 15;
    float bd = b_dt[n];
    float Aa = -expf(A_log[n]);
    size_t base = ((size_t)(b * SSZ + c * CLEN)) * NSZ + n;
    float h = 0.0f, p = 1.0f;
    #pragma unroll 4
    for (int t = 0; t < CLEN; t++) {
        float abar, inp;
        transform(g_buf0[base], g_buf1[base], x[base], bd, Aa, abar, inp);
        h = abar * h + inp;
        p *= abar;
        base += NSZ;
    }
    g_prod[gid] = p;
    g_hend[gid] = h;
}

__global__ void scan_pass2()
{
    int gid = blockIdx.x * blockDim.x + threadIdx.x;
    int n = gid & (NSZ - 1);
    int b = gid >> 11;
    float hin = 0.0f;
    #pragma unroll
    for (int c = 0; c < NCHUNK; c++) {
        int ci = (b * NCHUNK + c) * NSZ + n;
        g_hin[ci] = hin;
        hin = g_prod[ci] * hin + g_hend[ci];
    }
}

__global__ void scan_pass3(const float* __restrict__ x,
                           const float* __restrict__ b_dt,
                           const float* __restrict__ A_log)
{
    int gid = blockIdx.x * blockDim.x + threadIdx.x;
    int n = gid & (NSZ - 1);
    int c = (gid >> 11) & (NCHUNK - 1);
    int b = gid >> 15;
    float bd = b_dt[n];
    float Aa = -expf(A_log[n]);
    size_t base = ((size_t)(b * SSZ + c * CLEN)) * NSZ + n;
    float h = g_hin[gid];
    #pragma unroll 4
    for (int t = 0; t < CLEN; t++) {
        float abar, inp;
        transform(g_buf0[base], g_buf1[base], x[base], bd, Aa, abar, inp);
        h = abar * h + inp;
        g_hh[base] = __float2half_rn(h);     // fp16 for GEMM3 A operand
        base += NSZ;
    }
}

// ---------------------------------------------------------------------------
extern "C" void kernel_launch(void* const* d_in, const int* in_sizes, int n_in,
                              void* d_out, int out_size)
{
    const float* x      = (const float*)d_in[0];
    const float* W_dt   = (const float*)d_in[1];
    const float* b_dt   = (const float*)d_in[2];
    const float* W_B    = (const float*)d_in[3];
    const float* W_C    = (const float*)d_in[4];
    const float* A_log  = (const float*)d_in[5];
    const float* D_skip = (const float*)d_in[6];
    float* out = (float*)d_out;

    float *buf0, *buf1;
    __half *xh, *wh, *hh;
    cudaGetSymbolAddress((void**)&buf0, g_buf0);
    cudaGetSymbolAddress((void**)&buf1, g_buf1);
    cudaGetSymbolAddress((void**)&xh, g_xh);
    cudaGetSymbolAddress((void**)&wh, g_wh);
    cudaGetSymbolAddress((void**)&hh, g_hh);
    __half* wc_h = wh + 2 * (size_t)NSZ * KSZ;

    cudaFuncSetAttribute(gemm_tc<0>, cudaFuncAttributeMaxDynamicSharedMemorySize, SMEM_BYTES);
    cudaFuncSetAttribute(gemm_tc<1>, cudaFuncAttributeMaxDynamicSharedMemorySize, SMEM_BYTES);

    // fp16 conversions (W_dt and W_B land contiguously -> stacked N=4096)
    tohalf_k<<<(MSZ * (size_t)KSZ) / 4 / 256, 256>>>(x, xh);
    tohalf_k<<<(NSZ * (size_t)KSZ) / 4 / 256, 256>>>(W_dt, wh);
    tohalf_k<<<(NSZ * (size_t)KSZ) / 4 / 256, 256>>>(W_B,  wh + (size_t)NSZ * KSZ);
    tohalf_k<<<(NSZ * (size_t)KSZ) / 4 / 256, 256>>>(W_C,  wc_h);

    // dt_lin & Bp in ONE GEMM over stacked N=4096
    dim3 grid12(2 * NSZ / BN, MSZ / BM);   // (32, 64)
    gemm_tc<0><<<grid12, 128, SMEM_BYTES>>>(xh, wh, buf0, buf1, nullptr, nullptr);

    // fused transform + chunked selective scan
    scan_pass1<<<(BSZ * NCHUNK * NSZ) / 256, 256>>>(x, b_dt, A_log);
    scan_pass2<<<(BSZ * NSZ) / 256, 256>>>();
    scan_pass3<<<(BSZ * NCHUNK * NSZ) / 256, 256>>>(x, b_dt, A_log);

    // out = h @ W_C^T + D_skip * x   (skip fused in epilogue)
    dim3 grid3(NSZ / BN, MSZ / BM);        // (16, 64)
    gemm_tc<1><<<grid3, 128, SMEM_BYTES>>>(hh, wc_h, out, nullptr, x, D_skip);
}